// round 3
// baseline (speedup 1.0000x reference)
#include <cuda_runtime.h>
#include <cuda_bf16.h>

constexpr int D    = 272;    // capsule feature dim
constexpr int NC   = 19;     // classes
constexpr int NCP  = 20;     // padded classes (10 f32x2 pairs)
constexpr int ROWP = 32;     // proj row padded to 32 floats = 128 B (line aligned)
constexpr int MAXROWS = 65536;
constexpr int MAXNI   = 65536;

constexpr int PROJ_TILE   = 128;   // rows per proj block (1 per thread)
constexpr int NT_PRE      = 128;

__device__ __align__(128) float g_proj[MAXROWS * ROWP];   // 8.4 MB, L2-resident
__device__ int g_starts[MAXNI + 1];

// ---------------------------------------------------------------------------
// Fused kernel: bounds blocks first (finish fast), then proj blocks.
// ---------------------------------------------------------------------------
__global__ __launch_bounds__(NT_PRE)
void pre_kernel(const float* __restrict__ feats,   // [rows, D]
                const float* __restrict__ Wm,      // [D, NC]
                const int*   __restrict__ seg,     // [P] sorted
                int P, int NI, int rows, int boundsBlocks)
{
    const int t = threadIdx.x;

    if ((int)blockIdx.x < boundsBlocks) {
        // ---- segment boundaries: each thread handles 4 consecutive elems ----
        int e0 = (blockIdx.x * NT_PRE + t) * 4;
        if (e0 >= P) return;
        int prev = (e0 == 0) ? -1 : __ldg(seg + e0 - 1);
        if (e0 + 3 < P) {
            int4 v = __ldg(reinterpret_cast<const int4*>(seg + e0));
            int vs[4] = {v.x, v.y, v.z, v.w};
            #pragma unroll
            for (int j = 0; j < 4; ++j) {
                for (int q = prev + 1; q <= vs[j]; ++q) g_starts[q] = e0 + j;
                prev = vs[j];
            }
            if (e0 + 4 == P)
                for (int q = prev + 1; q <= NI; ++q) g_starts[q] = P;
        } else {
            for (int e = e0; e < P; ++e) {
                int s = __ldg(seg + e);
                for (int q = prev + 1; q <= s; ++q) g_starts[q] = e;
                prev = s;
                if (e == P - 1)
                    for (int q = s + 1; q <= NI; ++q) g_starts[q] = P;
            }
        }
        return;
    }

    // ---- projection: proj[r, c] = sum_d feats[r,d] * W[d,c], c padded to 20
    __shared__ float Ws[D * NCP];              // 21760 B, [d][20]
    __shared__ float Fs[PROJ_TILE * 17];       // 8704 B, chunk of 16 d, pad 17

    for (int i = t; i < D * NCP; i += NT_PRE) {
        int c = i % NCP, d = i / NCP;
        Ws[i] = (c < NC) ? __ldg(Wm + d * NC + c) : 0.0f;
    }

    const int rowbase = ((int)blockIdx.x - boundsBlocks) * PROJ_TILE;
    const int myrow   = min(rowbase + t, rows - 1);

    unsigned long long acc[10];
    #pragma unroll
    for (int c = 0; c < 10; ++c) acc[c] = 0ULL;

    for (int dc = 0; dc < D; dc += 16) {
        __syncthreads();   // Fs reuse (first iter: Ws visibility)
        // Stage 128 rows x 16 floats = 512 float4 (4 per thread), coalesced 64B/row
        #pragma unroll
        for (int i = 0; i < 4; ++i) {
            int fid = i * NT_PRE + t;          // 0..511
            int r   = fid >> 2, q = fid & 3;
            int gr  = min(rowbase + r, rows - 1);
            float4 v = __ldg(reinterpret_cast<const float4*>(
                                 feats + (size_t)gr * D + dc) + q);
            float* dst = &Fs[r * 17 + q * 4];
            dst[0] = v.x; dst[1] = v.y; dst[2] = v.z; dst[3] = v.w;
        }
        __syncthreads();

        #pragma unroll
        for (int dd = 0; dd < 16; ++dd) {
            float fa = Fs[t * 17 + dd];
            unsigned long long pa;
            asm("mov.b64 %0, {%1, %1};" : "=l"(pa) : "f"(fa));
            const ulonglong2* wv = reinterpret_cast<const ulonglong2*>(
                Ws + (dc + dd) * NCP);
            ulonglong2 w0 = wv[0], w1 = wv[1], w2 = wv[2], w3 = wv[3], w4 = wv[4];
            asm("fma.rn.f32x2 %0, %1, %2, %0;" : "+l"(acc[0]) : "l"(pa), "l"(w0.x));
            asm("fma.rn.f32x2 %0, %1, %2, %0;" : "+l"(acc[1]) : "l"(pa), "l"(w0.y));
            asm("fma.rn.f32x2 %0, %1, %2, %0;" : "+l"(acc[2]) : "l"(pa), "l"(w1.x));
            asm("fma.rn.f32x2 %0, %1, %2, %0;" : "+l"(acc[3]) : "l"(pa), "l"(w1.y));
            asm("fma.rn.f32x2 %0, %1, %2, %0;" : "+l"(acc[4]) : "l"(pa), "l"(w2.x));
            asm("fma.rn.f32x2 %0, %1, %2, %0;" : "+l"(acc[5]) : "l"(pa), "l"(w2.y));
            asm("fma.rn.f32x2 %0, %1, %2, %0;" : "+l"(acc[6]) : "l"(pa), "l"(w3.x));
            asm("fma.rn.f32x2 %0, %1, %2, %0;" : "+l"(acc[7]) : "l"(pa), "l"(w3.y));
            asm("fma.rn.f32x2 %0, %1, %2, %0;" : "+l"(acc[8]) : "l"(pa), "l"(w4.x));
            asm("fma.rn.f32x2 %0, %1, %2, %0;" : "+l"(acc[9]) : "l"(pa), "l"(w4.y));
        }
    }

    if (rowbase + t < rows) {
        float2 u[10];
        #pragma unroll
        for (int c = 0; c < 10; ++c)
            asm("mov.b64 {%0, %1}, %2;" : "=f"(u[c].x), "=f"(u[c].y) : "l"(acc[c]));
        float4* o = reinterpret_cast<float4*>(g_proj + (size_t)myrow * ROWP);
        o[0] = make_float4(u[0].x, u[0].y, u[1].x, u[1].y);
        o[1] = make_float4(u[2].x, u[2].y, u[3].x, u[3].y);
        o[2] = make_float4(u[4].x, u[4].y, u[5].x, u[5].y);
        o[3] = make_float4(u[6].x, u[6].y, u[7].x, u[7].y);
        o[4] = make_float4(u[8].x, u[8].y, u[9].x, u[9].y);
        // pad lanes 20..31 = 0 so gather lanes can read anything safely
        float4 z = make_float4(0.f, 0.f, 0.f, 0.f);
        o[5] = z; o[6] = z; o[7] = z;
    }
}

// ---------------------------------------------------------------------------
// Gather: block per segment, 8 warps; each warp-inst reads ONE point's padded
// row (lanes 0..19 -> 80 B within one 128 B line = 1 wavefront), lane c = class.
// ---------------------------------------------------------------------------
__global__ __launch_bounds__(256)
void gather_kernel(const int* __restrict__ pidx,
                   const float* __restrict__ bias,
                   float* __restrict__ out)
{
    const int s = blockIdx.x;
    const int t = threadIdx.x;
    const int w = t >> 5;          // warp 0..7: point phase
    const int c = t & 31;          // lane: class (20..31 discarded)

    const int start = g_starts[s];
    const int end   = g_starts[s + 1];

    const int cc = min(c, NCP - 1);     // keep all lanes converged, same line
    float acc = 0.f;

    int k = start + w;
    for (; k + 24 < end; k += 32) {
        int i0 = __ldg(pidx + k);
        int i1 = __ldg(pidx + k + 8);
        int i2 = __ldg(pidx + k + 16);
        int i3 = __ldg(pidx + k + 24);
        float v0 = __ldg(g_proj + (size_t)i0 * ROWP + cc);
        float v1 = __ldg(g_proj + (size_t)i1 * ROWP + cc);
        float v2 = __ldg(g_proj + (size_t)i2 * ROWP + cc);
        float v3 = __ldg(g_proj + (size_t)i3 * ROWP + cc);
        acc += (v0 + v1) + (v2 + v3);
    }
    for (; k < end; k += 8)
        acc += __ldg(g_proj + (size_t)__ldg(pidx + k) * ROWP + cc);

    __shared__ float sm[8][NCP];
    if (c < NCP) sm[w][c] = acc;
    __syncthreads();

    if (t < NC) {
        int count  = end - start;
        float invc = 1.0f / (float)max(count, 1);
        float v = 0.f;
        #pragma unroll
        for (int j = 0; j < 8; ++j) v += sm[j][t];
        v = v * invc + __ldg(bias + t);
        out[(size_t)s * NC + t] = 1.0f / (1.0f + __expf(-v));
    }
}

// ---------------------------------------------------------------------------
extern "C" void kernel_launch(void* const* d_in, const int* in_sizes, int n_in,
                              void* d_out, int out_size) {
    const float* feats = (const float*)d_in[0];   // [B,H,Wd,D]
    const float* Wm    = (const float*)d_in[1];   // [D, NC]
    const float* bias  = (const float*)d_in[2];   // [NC]
    const int*   pidx  = (const int*)d_in[3];     // [P]
    const int*   seg   = (const int*)d_in[4];     // [P] sorted
    const int    P     = in_sizes[3];
    const int    rows  = in_sizes[0] / D;         // 65536
    const int    NI    = out_size / NC;           // 4096

    const int boundsBlocks = (P + NT_PRE * 4 - 1) / (NT_PRE * 4);   // 1024
    const int projBlocks   = (rows + PROJ_TILE - 1) / PROJ_TILE;    // 512

    pre_kernel<<<boundsBlocks + projBlocks, NT_PRE>>>(feats, Wm, seg,
                                                      P, NI, rows, boundsBlocks);
    gather_kernel<<<NI, 256>>>(pidx, bias, (float*)d_out);
}

// round 4
// speedup vs baseline: 1.0133x; 1.0133x over previous
#include <cuda_runtime.h>
#include <cuda_bf16.h>

constexpr int D    = 272;    // capsule feature dim
constexpr int NC   = 19;     // classes
constexpr int NCP  = 20;     // padded classes (10 f32x2 pairs)
constexpr int ROWP = 32;     // proj row stride: 32 floats = 128 B (line aligned)
constexpr int MAXROWS = 65536;
constexpr int MAXNI   = 65536;

constexpr int PROJ_TILE = 128;   // rows per proj block (1 per thread)
constexpr int NT_PRE    = 128;

__device__ __align__(128) float g_proj[MAXROWS * ROWP];   // 8.4 MB (only 80 B/row used)
__device__ int g_starts[MAXNI + 1];

// ---------------------------------------------------------------------------
// Fused kernel: bounds blocks first (finish fast), then proj blocks.
// ---------------------------------------------------------------------------
__global__ __launch_bounds__(NT_PRE)
void pre_kernel(const float* __restrict__ feats,   // [rows, D]
                const float* __restrict__ Wm,      // [D, NC]
                const int*   __restrict__ seg,     // [P] sorted
                int P, int NI, int rows, int boundsBlocks)
{
    const int t = threadIdx.x;

    if ((int)blockIdx.x < boundsBlocks) {
        // ---- segment boundaries: each thread handles 4 consecutive elems ----
        int e0 = (blockIdx.x * NT_PRE + t) * 4;
        if (e0 >= P) return;
        int prev = (e0 == 0) ? -1 : __ldg(seg + e0 - 1);
        if (e0 + 3 < P) {
            int4 v = __ldg(reinterpret_cast<const int4*>(seg + e0));
            int vs[4] = {v.x, v.y, v.z, v.w};
            #pragma unroll
            for (int j = 0; j < 4; ++j) {
                for (int q = prev + 1; q <= vs[j]; ++q) g_starts[q] = e0 + j;
                prev = vs[j];
            }
            if (e0 + 4 == P)
                for (int q = prev + 1; q <= NI; ++q) g_starts[q] = P;
        } else {
            for (int e = e0; e < P; ++e) {
                int s = __ldg(seg + e);
                for (int q = prev + 1; q <= s; ++q) g_starts[q] = e;
                prev = s;
                if (e == P - 1)
                    for (int q = s + 1; q <= NI; ++q) g_starts[q] = P;
            }
        }
        return;
    }

    // ---- projection: proj[r, c] = sum_d feats[r,d] * W[d,c], c in f32x2 pairs
    __shared__ float Ws[D * NCP];              // 21760 B, [d][20]
    __shared__ float Fs[PROJ_TILE * 17];       // 8704 B, 16-d chunk, pad 17

    for (int i = t; i < D * NCP; i += NT_PRE) {
        int c = i % NCP, d = i / NCP;
        Ws[i] = (c < NC) ? __ldg(Wm + d * NC + c) : 0.0f;
    }

    const int rowbase = ((int)blockIdx.x - boundsBlocks) * PROJ_TILE;
    const int myrow   = min(rowbase + t, rows - 1);

    unsigned long long acc[10];
    #pragma unroll
    for (int c = 0; c < 10; ++c) acc[c] = 0ULL;

    for (int dc = 0; dc < D; dc += 16) {
        __syncthreads();   // Fs reuse (first iter: Ws visibility)
        // Stage 128 rows x 16 floats = 512 float4 (4/thread), 64B/row coalesced
        #pragma unroll
        for (int i = 0; i < 4; ++i) {
            int fid = i * NT_PRE + t;          // 0..511
            int r   = fid >> 2, q = fid & 3;
            int gr  = min(rowbase + r, rows - 1);
            float4 v = __ldg(reinterpret_cast<const float4*>(
                                 feats + (size_t)gr * D + dc) + q);
            float* dst = &Fs[r * 17 + q * 4];
            dst[0] = v.x; dst[1] = v.y; dst[2] = v.z; dst[3] = v.w;
        }
        __syncthreads();

        // Moderate unroll + LDS.64 weight loads (R2-proven: no spill)
        #pragma unroll 4
        for (int dd = 0; dd < 16; ++dd) {
            float fa = Fs[t * 17 + dd];
            unsigned long long pa;
            asm("mov.b64 %0, {%1, %1};" : "=l"(pa) : "f"(fa));
            const unsigned long long* wrow =
                reinterpret_cast<const unsigned long long*>(Ws + (dc + dd) * NCP);
            #pragma unroll
            for (int c = 0; c < 10; ++c) {
                unsigned long long w = wrow[c];
                asm("fma.rn.f32x2 %0, %1, %2, %0;" : "+l"(acc[c]) : "l"(pa), "l"(w));
            }
        }
    }

    if (rowbase + t < rows) {
        float2 u[10];
        #pragma unroll
        for (int c = 0; c < 10; ++c)
            asm("mov.b64 {%0, %1}, %2;" : "=f"(u[c].x), "=f"(u[c].y) : "l"(acc[c]));
        float4* o = reinterpret_cast<float4*>(g_proj + (size_t)myrow * ROWP);
        o[0] = make_float4(u[0].x, u[0].y, u[1].x, u[1].y);
        o[1] = make_float4(u[2].x, u[2].y, u[3].x, u[3].y);
        o[2] = make_float4(u[4].x, u[4].y, u[5].x, u[5].y);
        o[3] = make_float4(u[6].x, u[6].y, u[7].x, u[7].y);
        o[4] = make_float4(u[8].x, u[8].y, u[9].x, u[9].y);
        // no pad stores: gather lanes clamp to class 19, never read 20..31
    }
}

// ---------------------------------------------------------------------------
// Gather: block per segment, 8 warps. Indices staged through smem (kills the
// idx->val dependent chain); each warp-inst reads ONE point's row, lanes 0..19
// (80 B in one 128 B line = 1 wavefront), lane c = class.
// ---------------------------------------------------------------------------
__global__ __launch_bounds__(256)
void gather_kernel(const int* __restrict__ pidx,
                   const float* __restrict__ bias,
                   float* __restrict__ out)
{
    const int s = blockIdx.x;
    const int t = threadIdx.x;
    const int w = t >> 5;          // warp 0..7: point phase
    const int c = t & 31;          // lane: class
    const int cc = min(c, NC - 1); // lanes 19..31 converge on class 19's address

    const int start = g_starts[s];
    const int end   = g_starts[s + 1];

    __shared__ int   sidx[256];
    __shared__ float sm[8][NCP];

    float acc = 0.f;

    for (int base = start; base < end; base += 256) {
        const int n = min(256, end - base);
        __syncthreads();                       // sidx reuse
        if (t < n) sidx[t] = __ldg(pidx + base + t);
        __syncthreads();
        int k = w;
        for (; k + 24 < n; k += 32) {
            int i0 = sidx[k], i1 = sidx[k + 8], i2 = sidx[k + 16], i3 = sidx[k + 24];
            float v0 = __ldg(g_proj + (size_t)i0 * ROWP + cc);
            float v1 = __ldg(g_proj + (size_t)i1 * ROWP + cc);
            float v2 = __ldg(g_proj + (size_t)i2 * ROWP + cc);
            float v3 = __ldg(g_proj + (size_t)i3 * ROWP + cc);
            acc += (v0 + v1) + (v2 + v3);
        }
        for (; k < n; k += 8)
            acc += __ldg(g_proj + (size_t)sidx[k] * ROWP + cc);
    }

    if (c < NCP) sm[w][c] = acc;
    __syncthreads();

    if (t < NC) {
        int count  = end - start;
        float invc = 1.0f / (float)max(count, 1);
        float v = 0.f;
        #pragma unroll
        for (int j = 0; j < 8; ++j) v += sm[j][t];
        v = v * invc + __ldg(bias + t);
        out[(size_t)s * NC + t] = 1.0f / (1.0f + __expf(-v));
    }
}

// ---------------------------------------------------------------------------
extern "C" void kernel_launch(void* const* d_in, const int* in_sizes, int n_in,
                              void* d_out, int out_size) {
    const float* feats = (const float*)d_in[0];   // [B,H,Wd,D]
    const float* Wm    = (const float*)d_in[1];   // [D, NC]
    const float* bias  = (const float*)d_in[2];   // [NC]
    const int*   pidx  = (const int*)d_in[3];     // [P]
    const int*   seg   = (const int*)d_in[4];     // [P] sorted
    const int    P     = in_sizes[3];
    const int    rows  = in_sizes[0] / D;         // 65536
    const int    NI    = out_size / NC;           // 4096

    const int boundsBlocks = (P + NT_PRE * 4 - 1) / (NT_PRE * 4);   // 1024
    const int projBlocks   = (rows + PROJ_TILE - 1) / PROJ_TILE;    // 512

    pre_kernel<<<boundsBlocks + projBlocks, NT_PRE>>>(feats, Wm, seg,
                                                      P, NI, rows, boundsBlocks);
    gather_kernel<<<NI, 256>>>(pidx, bias, (float*)d_out);
}